// round 2
// baseline (speedup 1.0000x reference)
#include <cuda_runtime.h>
#include <cuda_bf16.h>
#include <float.h>

#define N_NODES 50000
#define N_EDGES 800000
#define F_IN 128
#define H 256

// -------- device scratch (no allocs allowed) --------
__device__ float g_AGG[(size_t)N_NODES * H];   // segment-max output (128 or 256 cols)
__device__ float g_H1 [(size_t)N_NODES * H];
__device__ float g_H2 [(size_t)N_NODES * H];
__device__ float g_HT [(size_t)N_NODES * H];
__device__ int   g_deg[N_NODES];
__device__ int   g_rowptr[N_NODES + 1];
__device__ int   g_cursor[N_NODES];
__device__ int   g_csrsrc[N_EDGES];
__device__ int   g_is64;

// -------- edge dtype detect (int32 vs int64) --------
__global__ void detect_kernel(const int* e) {
    if (threadIdx.x == 0 && blockIdx.x == 0) {
        int ok = 1;
        #pragma unroll 1
        for (int i = 0; i < 64; i++) {
            if (e[2 * i + 1] != 0) { ok = 0; break; }
        }
        g_is64 = ok;
    }
}

__global__ void zero_deg_kernel() {
    int i = blockIdx.x * blockDim.x + threadIdx.x;
    if (i < N_NODES) g_deg[i] = 0;
}

__global__ void count_kernel(const void* __restrict__ ei) {
    int e = blockIdx.x * blockDim.x + threadIdx.x;
    if (e >= N_EDGES) return;
    int d;
    if (g_is64) d = (int)((const long long*)ei)[(size_t)N_EDGES + e];
    else        d = ((const int*)ei)[N_EDGES + e];
    atomicAdd(&g_deg[d], 1);
}

// single-block exclusive scan over degrees -> rowptr, cursor
__global__ void scan_kernel() {
    __shared__ int s[1024];
    const int tid = threadIdx.x;
    const int CH = (N_NODES + 1023) / 1024;
    int beg = tid * CH;
    int end = beg + CH; if (end > N_NODES) end = N_NODES;
    int sum = 0;
    for (int i = beg; i < end; i++) sum += g_deg[i];
    s[tid] = sum;
    __syncthreads();
    for (int off = 1; off < 1024; off <<= 1) {
        int v = (tid >= off) ? s[tid - off] : 0;
        __syncthreads();
        s[tid] += v;
        __syncthreads();
    }
    int run = s[tid] - sum;   // exclusive prefix for this chunk
    for (int i = beg; i < end; i++) {
        g_rowptr[i] = run;
        g_cursor[i] = run;
        run += g_deg[i];
    }
    if (tid == 1023) g_rowptr[N_NODES] = s[1023];
}

__global__ void scatter_kernel(const void* __restrict__ ei) {
    int e = blockIdx.x * blockDim.x + threadIdx.x;
    if (e >= N_EDGES) return;
    int sN, dN;
    if (g_is64) {
        sN = (int)((const long long*)ei)[e];
        dN = (int)((const long long*)ei)[(size_t)N_EDGES + e];
    } else {
        sN = ((const int*)ei)[e];
        dN = ((const int*)ei)[N_EDGES + e];
    }
    int pos = atomicAdd(&g_cursor[dN], 1);
    g_csrsrc[pos] = sN;
}

// -------- segment max: one warp per node, float4 vectorized --------
__device__ __forceinline__ float4 max4(float4 a, float4 b) {
    return make_float4(fmaxf(a.x, b.x), fmaxf(a.y, b.y),
                       fmaxf(a.z, b.z), fmaxf(a.w, b.w));
}

template <int F>
__global__ void segmax_kernel(const float* __restrict__ feat, float* __restrict__ out) {
    int w = (blockIdx.x * blockDim.x + threadIdx.x) >> 5;
    int lane = threadIdx.x & 31;
    if (w >= N_NODES) return;
    int beg = g_rowptr[w];
    int end = g_rowptr[w + 1];
    constexpr int NV = F / 128;      // float4 per lane
    float4 m[NV];
    #pragma unroll
    for (int v = 0; v < NV; v++) m[v] = make_float4(-FLT_MAX, -FLT_MAX, -FLT_MAX, -FLT_MAX);

    int e = beg;
    for (; e + 1 < end; e += 2) {
        int s0 = g_csrsrc[e];
        int s1 = g_csrsrc[e + 1];
        const float4* r0 = (const float4*)(feat + (size_t)s0 * F);
        const float4* r1 = (const float4*)(feat + (size_t)s1 * F);
        #pragma unroll
        for (int v = 0; v < NV; v++) {
            float4 a = r0[lane + 32 * v];
            float4 b = r1[lane + 32 * v];
            m[v] = max4(m[v], max4(a, b));
        }
    }
    if (e < end) {
        int s0 = g_csrsrc[e];
        const float4* r0 = (const float4*)(feat + (size_t)s0 * F);
        #pragma unroll
        for (int v = 0; v < NV; v++) m[v] = max4(m[v], r0[lane + 32 * v]);
    }
    if (beg == end) {
        #pragma unroll
        for (int v = 0; v < NV; v++) m[v] = make_float4(0.f, 0.f, 0.f, 0.f);
    }
    float4* o = (float4*)(out + (size_t)w * F);
    #pragma unroll
    for (int v = 0; v < NV; v++) o[lane + 32 * v] = m[v];
}

// -------- fused dual-A SGEMM: C = relu(A1@W1 + A2@W2 + bias) --------
// BM=BN=128, BK=8, 256 threads, 8x8 microtile
#define BM 128
#define BN 128
#define BK 8

__global__ void __launch_bounds__(256, 2)
sage_gemm_kernel(const float* __restrict__ A1, const float* __restrict__ W1,
                 const float* __restrict__ A2, const float* __restrict__ W2,
                 const float* __restrict__ bias, float* __restrict__ C,
                 int M, int k1, int k2, int ncols) {
    __shared__ float As[BK][BM + 4];
    __shared__ float Ws[BK][BN + 4];

    const int tid = threadIdx.x;
    const int tx = tid & 15;        // 0..15 -> col group
    const int ty = tid >> 4;        // 0..15 -> row group
    const int row0 = blockIdx.x * BM;
    const int col0 = blockIdx.y * BN;

    // load mapping
    const int ar = tid >> 1;              // 0..127 tile row
    const int ak = (tid & 1) * 4;         // k offset 0/4
    const int wk = tid >> 5;              // 0..7 tile k row
    const int wn = (tid & 31) * 4;        // 0..124 col offset

    float acc[8][8];
    #pragma unroll
    for (int i = 0; i < 8; i++)
        #pragma unroll
        for (int j = 0; j < 8; j++) acc[i][j] = 0.f;

    #pragma unroll 1
    for (int part = 0; part < 2; ++part) {
        const float* A = part ? A2 : A1;
        const float* W = part ? W2 : W1;
        const int K = part ? k2 : k1;
        #pragma unroll 1
        for (int k0 = 0; k0 < K; k0 += BK) {
            float4 av = make_float4(0.f, 0.f, 0.f, 0.f);
            int grow = row0 + ar;
            if (grow < M) av = *(const float4*)(A + (size_t)grow * K + k0 + ak);
            float4 wv = *(const float4*)(W + (size_t)(k0 + wk) * ncols + col0 + wn);

            __syncthreads();
            As[ak + 0][ar] = av.x;
            As[ak + 1][ar] = av.y;
            As[ak + 2][ar] = av.z;
            As[ak + 3][ar] = av.w;
            *(float4*)&Ws[wk][wn] = wv;
            __syncthreads();

            #pragma unroll
            for (int k = 0; k < BK; k++) {
                float4 a0 = *(const float4*)&As[k][ty * 8];
                float4 a1 = *(const float4*)&As[k][ty * 8 + 4];
                float4 w0 = *(const float4*)&Ws[k][tx * 8];
                float4 w1 = *(const float4*)&Ws[k][tx * 8 + 4];
                float a[8] = {a0.x, a0.y, a0.z, a0.w, a1.x, a1.y, a1.z, a1.w};
                float w[8] = {w0.x, w0.y, w0.z, w0.w, w1.x, w1.y, w1.z, w1.w};
                #pragma unroll
                for (int i = 0; i < 8; i++)
                    #pragma unroll
                    for (int j = 0; j < 8; j++)
                        acc[i][j] += a[i] * w[j];
            }
        }
    }

    // epilogue: bias + relu
    float wb[8];
    #pragma unroll
    for (int j = 0; j < 8; j++) wb[j] = bias[col0 + tx * 8 + j];

    #pragma unroll
    for (int i = 0; i < 8; i++) {
        int r = row0 + ty * 8 + i;
        if (r >= M) break;
        float4 o0, o1;
        o0.x = fmaxf(acc[i][0] + wb[0], 0.f);
        o0.y = fmaxf(acc[i][1] + wb[1], 0.f);
        o0.z = fmaxf(acc[i][2] + wb[2], 0.f);
        o0.w = fmaxf(acc[i][3] + wb[3], 0.f);
        o1.x = fmaxf(acc[i][4] + wb[4], 0.f);
        o1.y = fmaxf(acc[i][5] + wb[5], 0.f);
        o1.z = fmaxf(acc[i][6] + wb[6], 0.f);
        o1.w = fmaxf(acc[i][7] + wb[7], 0.f);
        float* cp = C + (size_t)r * ncols + col0 + tx * 8;
        *(float4*)(cp)     = o0;
        *(float4*)(cp + 4) = o1;
    }
}

// -------- head: out[n] = dot(h[n,:256], w) + b --------
__global__ void head_kernel(const float* __restrict__ h, const float* __restrict__ wv,
                            const float* __restrict__ b, float* __restrict__ out) {
    int node = (blockIdx.x * blockDim.x + threadIdx.x) >> 5;
    int lane = threadIdx.x & 31;
    if (node >= N_NODES) return;
    const float* row = h + (size_t)node * H;
    float s = 0.f;
    #pragma unroll
    for (int i = 0; i < H / 32; i++) s += row[lane + 32 * i] * wv[lane + 32 * i];
    #pragma unroll
    for (int off = 16; off > 0; off >>= 1) s += __shfl_xor_sync(0xffffffffu, s, off);
    if (lane == 0) out[node] = s + b[0];
}

extern "C" void kernel_launch(void* const* d_in, const int* in_sizes, int n_in,
                              void* d_out, int out_size) {
    const float* x   = (const float*)d_in[0];
    const void*  ei  = d_in[1];
    const float* Wl1 = (const float*)d_in[2];
    const float* bl1 = (const float*)d_in[3];
    const float* Wr1 = (const float*)d_in[4];
    const float* Wl2 = (const float*)d_in[5];
    const float* bl2 = (const float*)d_in[6];
    const float* Wr2 = (const float*)d_in[7];
    const float* Wla = (const float*)d_in[8];
    const float* bla = (const float*)d_in[9];
    const float* Wra = (const float*)d_in[10];
    const float* Wa  = (const float*)d_in[11];
    const float* ba  = (const float*)d_in[12];
    const float* Wlm = (const float*)d_in[13];
    const float* blm = (const float*)d_in[14];
    const float* Wrm = (const float*)d_in[15];
    const float* Wm  = (const float*)d_in[16];
    const float* bm  = (const float*)d_in[17];
    float* out = (float*)d_out;

    float* AGG; cudaGetSymbolAddress((void**)&AGG, g_AGG);
    float* H1;  cudaGetSymbolAddress((void**)&H1,  g_H1);
    float* H2;  cudaGetSymbolAddress((void**)&H2,  g_H2);
    float* HT;  cudaGetSymbolAddress((void**)&HT,  g_HT);

    const int TB = 256;
    dim3 gemm_grid((N_NODES + BM - 1) / BM, H / BN);

    // CSR build
    detect_kernel<<<1, 32>>>((const int*)ei);
    zero_deg_kernel<<<(N_NODES + TB - 1) / TB, TB>>>();
    count_kernel<<<(N_EDGES + TB - 1) / TB, TB>>>(ei);
    scan_kernel<<<1, 1024>>>();
    scatter_kernel<<<(N_EDGES + TB - 1) / TB, TB>>>(ei);

    const int warp_blocks = (N_NODES * 32 + TB - 1) / TB;

    // layer 1
    segmax_kernel<F_IN><<<warp_blocks, TB>>>(x, AGG);
    sage_gemm_kernel<<<gemm_grid, TB>>>(AGG, Wl1, x, Wr1, bl1, H1, N_NODES, F_IN, F_IN, H);

    // layer 2
    segmax_kernel<H><<<warp_blocks, TB>>>(H1, AGG);
    sage_gemm_kernel<<<gemm_grid, TB>>>(AGG, Wl2, H1, Wr2, bl2, H2, N_NODES, H, H, H);

    // shared aggregation for both branches
    segmax_kernel<H><<<warp_blocks, TB>>>(H2, AGG);

    // rtang branch
    sage_gemm_kernel<<<gemm_grid, TB>>>(AGG, Wla, H2, Wra, bla, HT, N_NODES, H, H, H);
    head_kernel<<<warp_blocks, TB>>>(HT, Wa, ba, out);

    // movedis branch
    sage_gemm_kernel<<<gemm_grid, TB>>>(AGG, Wlm, H2, Wrm, blm, HT, N_NODES, H, H, H);
    head_kernel<<<warp_blocks, TB>>>(HT, Wm, bm, out + N_NODES);
}

// round 4
// speedup vs baseline: 2.0395x; 2.0395x over previous
#include <cuda_runtime.h>
#include <cuda_bf16.h>
#include <float.h>
#include <stdint.h>

#define N_NODES 50000
#define N_EDGES 800000
#define F_IN 128
#define H 256
#define KC 32
#define GEMM_TM 128

// ---------------- device scratch (no allocs allowed) ----------------
__device__ float g_AGG[(size_t)N_NODES * H];
__device__ float g_H1 [(size_t)N_NODES * H];
__device__ float g_H2 [(size_t)N_NODES * H];
__device__ int   g_deg[N_NODES];
__device__ int   g_rowptr[N_NODES + 1];
__device__ int   g_cursor[N_NODES];
__device__ int   g_csrsrc[N_EDGES];
__device__ int   g_part[128];
__device__ int   g_is64;
// packed transposed bf16 hi/lo weights  Bt[n][k] (K-major)
__device__ __nv_bfloat16 g_Bt1h[256 * 256], g_Bt1l[256 * 256];
__device__ __nv_bfloat16 g_Bt2h[256 * 512], g_Bt2l[256 * 512];
__device__ __nv_bfloat16 g_Bt3h[512 * 512], g_Bt3l[512 * 512];
__device__ float g_b3[512], g_hw[512], g_hb[2];

__device__ __forceinline__ uint32_t smem_u32(const void* p) {
    uint32_t a;
    asm("{ .reg .u64 t; cvta.to.shared.u64 t, %1; cvt.u32.u64 %0, t; }" : "=r"(a) : "l"(p));
    return a;
}
__device__ __forceinline__ uint32_t b2u(__nv_bfloat162 h) {
    return *reinterpret_cast<uint32_t*>(&h);
}
__device__ __forceinline__ void ldsm_x4(uint32_t* r, uint32_t addr) {
    asm volatile("ldmatrix.sync.aligned.m8n8.x4.shared.b16 {%0,%1,%2,%3}, [%4];"
                 : "=r"(r[0]), "=r"(r[1]), "=r"(r[2]), "=r"(r[3]) : "r"(addr));
}
__device__ __forceinline__ void mma_bf16(float* c, const uint32_t* a, const uint32_t* b) {
    asm volatile(
        "mma.sync.aligned.m16n8k16.row.col.f32.bf16.bf16.f32 "
        "{%0,%1,%2,%3}, {%4,%5,%6,%7}, {%8,%9}, {%0,%1,%2,%3};"
        : "+f"(c[0]), "+f"(c[1]), "+f"(c[2]), "+f"(c[3])
        : "r"(a[0]), "r"(a[1]), "r"(a[2]), "r"(a[3]), "r"(b[0]), "r"(b[1]));
}

// ---------------- edge dtype detect (int32 vs int64) ----------------
__global__ void detect_kernel(const int* e) {
    if (threadIdx.x == 0 && blockIdx.x == 0) {
        int ok = 1;
        #pragma unroll 1
        for (int i = 0; i < 64; i++)
            if (e[2 * i + 1] != 0) { ok = 0; break; }
        g_is64 = ok;
    }
}

__global__ void zero_deg_kernel() {
    int i = blockIdx.x * blockDim.x + threadIdx.x;
    if (i < N_NODES) g_deg[i] = 0;
}

__global__ void count_kernel(const void* __restrict__ ei) {
    int e = blockIdx.x * blockDim.x + threadIdx.x;
    if (e >= N_EDGES) return;
    int d;
    if (g_is64) d = (int)((const long long*)ei)[(size_t)N_EDGES + e];
    else        d = ((const int*)ei)[N_EDGES + e];
    atomicAdd(&g_deg[d], 1);
}

// ---------------- 3-phase parallel scan ----------------
#define SCB 512
#define NBLK ((N_NODES + SCB - 1) / SCB)   // 98

__global__ void scan1_kernel() {
    __shared__ int s[SCB];
    int tid = threadIdx.x;
    int i = blockIdx.x * SCB + tid;
    s[tid] = (i < N_NODES) ? g_deg[i] : 0;
    __syncthreads();
    for (int off = SCB / 2; off > 0; off >>= 1) {
        if (tid < off) s[tid] += s[tid + off];
        __syncthreads();
    }
    if (tid == 0) g_part[blockIdx.x] = s[0];
}

__global__ void scan2_kernel() {
    __shared__ int s[128];
    int tid = threadIdx.x;
    int v = (tid < NBLK) ? g_part[tid] : 0;
    s[tid] = v;
    __syncthreads();
    for (int off = 1; off < 128; off <<= 1) {
        int t = (tid >= off) ? s[tid - off] : 0;
        __syncthreads();
        s[tid] += t;
        __syncthreads();
    }
    if (tid < NBLK) g_part[tid] = s[tid] - v;   // exclusive
}

__global__ void scan3_kernel() {
    __shared__ int s[SCB];
    int tid = threadIdx.x;
    int i = blockIdx.x * SCB + tid;
    int v = (i < N_NODES) ? g_deg[i] : 0;
    s[tid] = v;
    __syncthreads();
    for (int off = 1; off < SCB; off <<= 1) {
        int t = (tid >= off) ? s[tid - off] : 0;
        __syncthreads();
        s[tid] += t;
        __syncthreads();
    }
    int incl = s[tid];
    int base = g_part[blockIdx.x];
    if (i < N_NODES) {
        g_rowptr[i] = base + incl - v;
        g_cursor[i] = base + incl - v;
        if (i == N_NODES - 1) g_rowptr[N_NODES] = base + incl;
    }
}

__global__ void scatter_kernel(const void* __restrict__ ei) {
    int e = blockIdx.x * blockDim.x + threadIdx.x;
    if (e >= N_EDGES) return;
    int sN, dN;
    if (g_is64) {
        sN = (int)((const long long*)ei)[e];
        dN = (int)((const long long*)ei)[(size_t)N_EDGES + e];
    } else {
        sN = ((const int*)ei)[e];
        dN = ((const int*)ei)[N_EDGES + e];
    }
    int pos = atomicAdd(&g_cursor[dN], 1);
    g_csrsrc[pos] = sN;
}

// ---------------- segment max: one warp per node ----------------
__device__ __forceinline__ float4 max4(float4 a, float4 b) {
    return make_float4(fmaxf(a.x, b.x), fmaxf(a.y, b.y),
                       fmaxf(a.z, b.z), fmaxf(a.w, b.w));
}

template <int F>
__global__ void segmax_kernel(const float* __restrict__ feat, float* __restrict__ out) {
    int w = (blockIdx.x * blockDim.x + threadIdx.x) >> 5;
    int lane = threadIdx.x & 31;
    if (w >= N_NODES) return;
    int beg = g_rowptr[w];
    int end = g_rowptr[w + 1];
    constexpr int NV = F / 128;
    float4 m[NV];
    #pragma unroll
    for (int v = 0; v < NV; v++) m[v] = make_float4(-FLT_MAX, -FLT_MAX, -FLT_MAX, -FLT_MAX);

    int e = beg;
    for (; e + 1 < end; e += 2) {
        int s0 = g_csrsrc[e];
        int s1 = g_csrsrc[e + 1];
        const float4* r0 = (const float4*)(feat + (size_t)s0 * F);
        const float4* r1 = (const float4*)(feat + (size_t)s1 * F);
        #pragma unroll
        for (int v = 0; v < NV; v++)
            m[v] = max4(m[v], max4(r0[lane + 32 * v], r1[lane + 32 * v]));
    }
    if (e < end) {
        int s0 = g_csrsrc[e];
        const float4* r0 = (const float4*)(feat + (size_t)s0 * F);
        #pragma unroll
        for (int v = 0; v < NV; v++) m[v] = max4(m[v], r0[lane + 32 * v]);
    }
    if (beg == end) {
        #pragma unroll
        for (int v = 0; v < NV; v++) m[v] = make_float4(0.f, 0.f, 0.f, 0.f);
    }
    float4* o = (float4*)(out + (size_t)w * F);
    #pragma unroll
    for (int v = 0; v < NV; v++) o[lane + 32 * v] = m[v];
}

// ---------------- weight pack: Bt[n][k] = W[k][n], bf16 hi/lo ----------------
__global__ void pack_w_kernel(__nv_bfloat16* dh, __nv_bfloat16* dl,
                              const float* __restrict__ Wl, const float* __restrict__ Wr,
                              int k1, int K, int n_off) {
    int idx = blockIdx.x * blockDim.x + threadIdx.x;
    if (idx >= 256 * K) return;
    int n = idx / K, k = idx % K;
    float v = (k < k1) ? Wl[(size_t)k * 256 + n] : Wr[(size_t)(k - k1) * 256 + n];
    __nv_bfloat16 h = __float2bfloat16(v);
    __nv_bfloat16 l = __float2bfloat16(v - __bfloat162float(h));
    dh[(size_t)(n_off + n) * K + k] = h;
    dl[(size_t)(n_off + n) * K + k] = l;
}

__global__ void pack_head_kernel(const float* bla, const float* blm,
                                 const float* Wa, const float* Wm,
                                 const float* ba, const float* bm) {
    int i = threadIdx.x + blockIdx.x * blockDim.x;
    if (i < 256) {
        g_b3[i] = bla[i];       g_b3[256 + i] = blm[i];
        g_hw[i] = Wa[i];        g_hw[256 + i] = Wm[i];
    }
    if (i == 0) { g_hb[0] = ba[0]; g_hb[1] = bm[0]; }
}

__global__ void init_out_kernel(float* out) {
    int i = blockIdx.x * blockDim.x + threadIdx.x;
    if (i < 2 * N_NODES) out[i] = g_hb[i / N_NODES];
}

// ---------------- mma.sync split-bf16 GEMM ----------------
// C[m, nb..nb+127] = relu( [A1|A2][m,:K] @ Bt[nb..nb+127,:K]^T + bias )
// 3-term: Ahi*Bhi + Alo*Bhi + Ahi*Blo, fp32 accumulate.
// mode 0: write fp32 C (ncols=256). mode 1: head partial dot -> atomicAdd.
// smem rows padded to 80B (5 x 16B chunks) -> conflict-free ldmatrix.
#define ROWB 80
#define MAT_SZ (128 * ROWB)          // 10240
#define OFF_AH 0
#define OFF_AL MAT_SZ
#define OFF_BH (2 * MAT_SZ)
#define OFF_BL (3 * MAT_SZ)
#define STAGE_SZ (4 * MAT_SZ)        // 40960
#define GEMM_SMEM (2 * STAGE_SZ)     // 81920

__global__ void __launch_bounds__(256)
mma_gemm(const float* __restrict__ A1, const float* __restrict__ A2, int k1, int k2,
         const __nv_bfloat16* __restrict__ Bth, const __nv_bfloat16* __restrict__ Btl,
         const float* __restrict__ bias, const float* __restrict__ headw,
         float* __restrict__ Cout, int mode) {
    extern __shared__ char smem[];
    const uint32_t sb = smem_u32(smem);
    const int tid = threadIdx.x;
    const int lane = tid & 31, wid = tid >> 5;
    const int warp_m = (wid & 3) * 32;
    const int warp_n = (wid >> 2) * 64;
    const int row0 = blockIdx.x * GEMM_TM;
    const int nb = blockIdx.y * 128;
    const int K = k1 + k2;
    const int NCH = K / KC;
    const int ach = k1 / KC;

    // per-lane ldmatrix address components
    const int a_row_l = (lane & 7) + ((lane >> 3) & 1) * 8;
    const int a_csel  = lane >> 4;                 // 0/1
    const int b_row_l = (lane & 7) + ((lane >> 3) & 2) * 4;
    const int b_csel  = (lane >> 3) & 1;

    // global load mapping
    const int ar = tid >> 1;            // row 0..127
    const int ah = tid & 1;             // k half (16 elems)
    const int myrow = row0 + ar;
    const bool rok = myrow < N_NODES;

    float acc[2][8][4];
    #pragma unroll
    for (int mi = 0; mi < 2; mi++)
        #pragma unroll
        for (int ni = 0; ni < 8; ni++)
            #pragma unroll
            for (int j = 0; j < 4; j++) acc[mi][ni][j] = 0.f;

    float fa[16];
    uint4 pbh[2], pbl[2];

    // ---- load chunk 0 ----
    {
        const float* A = (0 < ach) ? A1 : A2;
        int stride = (0 < ach) ? k1 : k2;
        const float4* src = (const float4*)(A + (size_t)myrow * stride + ah * 16);
        #pragma unroll
        for (int i = 0; i < 4; i++) {
            float4 f = rok ? src[i] : make_float4(0.f, 0.f, 0.f, 0.f);
            fa[i * 4 + 0] = f.x; fa[i * 4 + 1] = f.y; fa[i * 4 + 2] = f.z; fa[i * 4 + 3] = f.w;
        }
        const uint4* sh = (const uint4*)(Bth + (size_t)(nb + ar) * K + ah * 16);
        const uint4* sl = (const uint4*)(Btl + (size_t)(nb + ar) * K + ah * 16);
        pbh[0] = sh[0]; pbh[1] = sh[1];
        pbl[0] = sl[0]; pbl[1] = sl[1];
    }
    // store chunk 0
    {
        char* stg = smem;
        uint32_t hi[8], lo[8];
        #pragma unroll
        for (int i = 0; i < 8; i++) {
            float x = fa[2 * i], y = fa[2 * i + 1];
            __nv_bfloat162 h2 = __floats2bfloat162_rn(x, y);
            float lx = x - __bfloat162float(h2.x);
            float ly = y - __bfloat162float(h2.y);
            __nv_bfloat162 l2 = __floats2bfloat162_rn(lx, ly);
            hi[i] = b2u(h2); lo[i] = b2u(l2);
        }
        char* da = stg + ar * ROWB + ah * 32;
        *(uint4*)(da + OFF_AH)      = make_uint4(hi[0], hi[1], hi[2], hi[3]);
        *(uint4*)(da + OFF_AH + 16) = make_uint4(hi[4], hi[5], hi[6], hi[7]);
        *(uint4*)(da + OFF_AL)      = make_uint4(lo[0], lo[1], lo[2], lo[3]);
        *(uint4*)(da + OFF_AL + 16) = make_uint4(lo[4], lo[5], lo[6], lo[7]);
        *(uint4*)(da + OFF_BH)      = pbh[0];
        *(uint4*)(da + OFF_BH + 16) = pbh[1];
        *(uint4*)(da + OFF_BL)      = pbl[0];
        *(uint4*)(da + OFF_BL + 16) = pbl[1];
    }
    __syncthreads();

    for (int ch = 0; ch < NCH; ++ch) {
        const bool more = (ch + 1 < NCH);
        // ---- prefetch chunk ch+1 into registers ----
        if (more) {
            int c = ch + 1;
            const float* A;
            int stride, kloc;
            if (c < ach) { A = A1; stride = k1; kloc = c * KC; }
            else         { A = A2; stride = k2; kloc = (c - ach) * KC; }
            const float4* src = (const float4*)(A + (size_t)myrow * stride + kloc + ah * 16);
            #pragma unroll
            for (int i = 0; i < 4; i++) {
                float4 f = rok ? src[i] : make_float4(0.f, 0.f, 0.f, 0.f);
                fa[i * 4 + 0] = f.x; fa[i * 4 + 1] = f.y; fa[i * 4 + 2] = f.z; fa[i * 4 + 3] = f.w;
            }
            const uint4* sh = (const uint4*)(Bth + (size_t)(nb + ar) * K + c * KC + ah * 16);
            const uint4* sl = (const uint4*)(Btl + (size_t)(nb + ar) * K + c * KC + ah * 16);
            pbh[0] = sh[0]; pbh[1] = sh[1];
            pbl[0] = sl[0]; pbl[1] = sl[1];
        }

        // ---- compute on stage ch&1 ----
        {
            const uint32_t stg = sb + (ch & 1) * STAGE_SZ;
            #pragma unroll
            for (int kb = 0; kb < 2; kb++) {
                uint32_t Ah[2][4], Al[2][4];
                #pragma unroll
                for (int mi = 0; mi < 2; mi++) {
                    uint32_t addr = stg + (warp_m + mi * 16 + a_row_l) * ROWB +
                                    (kb * 2 + a_csel) * 16;
                    ldsm_x4(Ah[mi], addr + OFF_AH);
                    ldsm_x4(Al[mi], addr + OFF_AL);
                }
                uint32_t Bh[4][4], Bl[4][4];
                #pragma unroll
                for (int nt = 0; nt < 4; nt++) {
                    uint32_t addr = stg + (warp_n + nt * 16 + b_row_l) * ROWB +
                                    (kb * 2 + b_csel) * 16;
                    ldsm_x4(Bh[nt], addr + OFF_BH);
                    ldsm_x4(Bl[nt], addr + OFF_BL);
                }
                #pragma unroll
                for (int mi = 0; mi < 2; mi++)
                    #pragma unroll
                    for (int ni = 0; ni < 8; ni++) {
                        const uint32_t* bp  = &Bh[ni >> 1][(ni & 1) * 2];
                        const uint32_t* blp = &Bl[ni >> 1][(ni & 1) * 2];
                        mma_bf16(acc[mi][ni], Ah[mi], bp);
                        mma_bf16(acc[mi][ni], Al[mi], bp);
                        mma_bf16(acc[mi][ni], Ah[mi], blp);
                    }
            }
        }

        // ---- store prefetched chunk into other stage ----
        if (more) {
            char* stg = smem + ((ch + 1) & 1) * STAGE_SZ;
            uint32_t hi[8], lo[8];
            #pragma unroll
            for (int i = 0; i < 8; i++) {
                float x = fa[2 * i], y = fa[2 * i + 1];
                __nv_bfloat162 h2 = __floats2bfloat162_rn(x, y);
                float lx = x - __bfloat162float(h2.x);
                float ly = y - __bfloat162float(h2.y);
                __nv_bfloat162 l2 = __floats2bfloat162_rn(lx, ly);
                hi[i] = b2u(h2); lo[i] = b2u(l2);
            }
            char* da = stg + ar * ROWB + ah * 32;
            *(uint4*)(da + OFF_AH)      = make_uint4(hi[0], hi[1], hi[2], hi[3]);
            *(uint4*)(da + OFF_AH + 16) = make_uint4(hi[4], hi[5], hi[6], hi[7]);
            *(uint4*)(da + OFF_AL)      = make_uint4(lo[0], lo[1], lo[2], lo[3]);
            *(uint4*)(da + OFF_AL + 16) = make_uint4(lo[4], lo[5], lo[6], lo[7]);
            *(uint4*)(da + OFF_BH)      = pbh[0];
            *(uint4*)(da + OFF_BH + 16) = pbh[1];
            *(uint4*)(da + OFF_BL)      = pbl[0];
            *(uint4*)(da + OFF_BL + 16) = pbl[1];
        }
        __syncthreads();
    }

    // ---- epilogue ----
    const int t4r = lane >> 2;
    const int t4c = (lane & 3) * 2;
    if (mode == 0) {
        #pragma unroll
        for (int mi = 0; mi < 2; mi++) {
            #pragma unroll
            for (int half = 0; half < 2; half++) {
                int row = row0 + warp_m + mi * 16 + half * 8 + t4r;
                if (row >= N_NODES) continue;
                float* cp = Cout + (size_t)row * 256;
                #pragma unroll
                for (int ni = 0; ni < 8; ni++) {
                    int col = nb + warp_n + ni * 8 + t4c;
                    float v0 = fmaxf(acc[mi][ni][half * 2 + 0] + bias[col], 0.f);
                    float v1 = fmaxf(acc[mi][ni][half * 2 + 1] + bias[col + 1], 0.f);
                    *(float2*)(cp + col) = make_float2(v0, v1);
                }
            }
        }
    } else {
        const int branch = nb >> 8;   // 0 or 1
        #pragma unroll
        for (int mi = 0; mi < 2; mi++) {
            float s[2] = {0.f, 0.f};
            #pragma unroll
            for (int half = 0; half < 2; half++) {
                #pragma unroll
                for (int ni = 0; ni < 8; ni++) {
                    int col = nb + warp_n + ni * 8 + t4c;
                    float v0 = fmaxf(acc[mi][ni][half * 2 + 0] + bias[col], 0.f);
                    float v1 = fmaxf(acc[mi][ni][half * 2 + 1] + bias[col + 1], 0.f);
                    s[half] += v0 * headw[col] + v1 * headw[col + 1];
                }
            }
            #pragma unroll
            for (int half = 0; half < 2; half++) {
                float v = s[half];
                v += __shfl_xor_sync(0xffffffffu, v, 1);
                v += __shfl_xor_sync(0xffffffffu, v, 2);
                int row = row0 + warp_m + mi * 16 + half * 8 + t4r;
                if ((lane & 3) == 0 && row < N_NODES)
                    atomicAdd(&Cout[(size_t)branch * N_NODES + row], v);
            }
        }
    }
}

// ---------------- launch ----------------
extern "C" void kernel_launch(void* const* d_in, const int* in_sizes, int n_in,
                              void* d_out, int out_size) {
    const float* x   = (const float*)d_in[0];
    const void*  ei  = d_in[1];
    const float* Wl1 = (const float*)d_in[2];
    const float* bl1 = (const float*)d_in[3];
    const float* Wr1 = (const float*)d_in[4];
    const float* Wl2 = (const float*)d_in[5];
    const float* bl2 = (const float*)d_in[6];
    const float* Wr2 = (const float*)d_in[7];
    const float* Wla = (const float*)d_in[8];
    const float* bla = (const float*)d_in[9];
    const float* Wra = (const float*)d_in[10];
    const float* Wa  = (const float*)d_in[11];
    const float* ba  = (const float*)d_in[12];
    const float* Wlm = (const float*)d_in[13];
    const float* blm = (const float*)d_in[14];
    const float* Wrm = (const float*)d_in[15];
    const float* Wm  = (const float*)d_in[16];
    const float* bm  = (const float*)d_in[17];
    float* out = (float*)d_out;

    float* AGG; cudaGetSymbolAddress((void**)&AGG, g_AGG);
    float* H1;  cudaGetSymbolAddress((void**)&H1,  g_H1);
    float* H2;  cudaGetSymbolAddress((void**)&H2,  g_H2);
    __nv_bfloat16 *Bt1h, *Bt1l, *Bt2h, *Bt2l, *Bt3h, *Bt3l;
    cudaGetSymbolAddress((void**)&Bt1h, g_Bt1h);
    cudaGetSymbolAddress((void**)&Bt1l, g_Bt1l);
    cudaGetSymbolAddress((void**)&Bt2h, g_Bt2h);
    cudaGetSymbolAddress((void**)&Bt2l, g_Bt2l);
    cudaGetSymbolAddress((void**)&Bt3h, g_Bt3h);
    cudaGetSymbolAddress((void**)&Bt3l, g_Bt3l);
    float *b3, *hw;
    cudaGetSymbolAddress((void**)&b3, g_b3);
    cudaGetSymbolAddress((void**)&hw, g_hw);

    cudaFuncSetAttribute(mma_gemm, cudaFuncAttributeMaxDynamicSharedMemorySize, GEMM_SMEM);

    const int TB = 256;
    const int gemm_gx = (N_NODES + GEMM_TM - 1) / GEMM_TM;   // 391

    // CSR build
    detect_kernel<<<1, 32>>>((const int*)ei);
    zero_deg_kernel<<<(N_NODES + TB - 1) / TB, TB>>>();
    count_kernel<<<(N_EDGES + TB - 1) / TB, TB>>>(ei);
    scan1_kernel<<<NBLK, SCB>>>();
    scan2_kernel<<<1, 128>>>();
    scan3_kernel<<<NBLK, SCB>>>();
    scatter_kernel<<<(N_EDGES + TB - 1) / TB, TB>>>(ei);

    // weight packs (independent of CSR)
    pack_w_kernel<<<(256 * 256 + TB - 1) / TB, TB>>>(Bt1h, Bt1l, Wl1, Wr1, 128, 256, 0);
    pack_w_kernel<<<(256 * 512 + TB - 1) / TB, TB>>>(Bt2h, Bt2l, Wl2, Wr2, 256, 512, 0);
    pack_w_kernel<<<(256 * 512 + TB - 1) / TB, TB>>>(Bt3h, Bt3l, Wla, Wra, 256, 512, 0);
    pack_w_kernel<<<(256 * 512 + TB - 1) / TB, TB>>>(Bt3h, Bt3l, Wlm, Wrm, 256, 512, 256);
    pack_head_kernel<<<1, 256>>>(bla, blm, Wa, Wm, ba, bm);
    init_out_kernel<<<(2 * N_NODES + TB - 1) / TB, TB>>>(out);

    const int warp_blocks = (N_NODES * 32 + TB - 1) / TB;

    // layer 1
    segmax_kernel<F_IN><<<warp_blocks, TB>>>(x, AGG);
    mma_gemm<<<dim3(gemm_gx, 2), 256, GEMM_SMEM>>>(AGG, x, 128, 128, Bt1h, Bt1l,
                                                   bl1, nullptr, H1, 0);
    // layer 2
    segmax_kernel<H><<<warp_blocks, TB>>>(H1, AGG);
    mma_gemm<<<dim3(gemm_gx, 2), 256, GEMM_SMEM>>>(AGG, H1, 256, 256, Bt2h, Bt2l,
                                                   bl2, nullptr, H2, 0);
    // shared aggregation + fused dual-branch layer 3 with head epilogue
    segmax_kernel<H><<<warp_blocks, TB>>>(H2, AGG);
    mma_gemm<<<dim3(gemm_gx, 4), 256, GEMM_SMEM>>>(AGG, H2, 256, 256, Bt3h, Bt3l,
                                                   b3, hw, out, 1);
}

// round 6
// speedup vs baseline: 2.0642x; 1.0121x over previous
#include <cuda_runtime.h>
#include <cuda_bf16.h>
#include <float.h>
#include <stdint.h>

#define N_NODES 50000
#define N_EDGES 800000
#define F_IN 128
#define H 256
#define KC 32
#define GEMM_TM 128

// ---------------- device scratch (no allocs allowed) ----------------
__device__ float g_AGG[(size_t)N_NODES * H];
__device__ float g_H1 [(size_t)N_NODES * H];
__device__ float g_H2 [(size_t)N_NODES * H];
__device__ int   g_deg[N_NODES];
__device__ int   g_rowptr[N_NODES + 1];
__device__ int   g_cursor[N_NODES];
__device__ int   g_csrsrc[N_EDGES];
__device__ int   g_part[256];
__device__ int   g_bar;
// packed transposed bf16 hi/lo weights  Bt[n][k] (K-major)
__device__ __nv_bfloat16 g_Bt1h[256 * 256], g_Bt1l[256 * 256];
__device__ __nv_bfloat16 g_Bt2h[256 * 512], g_Bt2l[256 * 512];
__device__ __nv_bfloat16 g_Bt3h[512 * 512], g_Bt3l[512 * 512];
__device__ float g_b3[512], g_hw[512];

__device__ __forceinline__ uint32_t smem_u32(const void* p) {
    uint32_t a;
    asm("{ .reg .u64 t; cvta.to.shared.u64 t, %1; cvt.u32.u64 %0, t; }" : "=r"(a) : "l"(p));
    return a;
}
__device__ __forceinline__ uint32_t b2u(__nv_bfloat162 h) {
    return *reinterpret_cast<uint32_t*>(&h);
}
__device__ __forceinline__ void ldsm_x4(uint32_t* r, uint32_t addr) {
    asm volatile("ldmatrix.sync.aligned.m8n8.x4.shared.b16 {%0,%1,%2,%3}, [%4];"
                 : "=r"(r[0]), "=r"(r[1]), "=r"(r[2]), "=r"(r[3]) : "r"(addr));
}
__device__ __forceinline__ void mma_bf16(float* c, const uint32_t* a, const uint32_t* b) {
    asm volatile(
        "mma.sync.aligned.m16n8k16.row.col.f32.bf16.bf16.f32 "
        "{%0,%1,%2,%3}, {%4,%5,%6,%7}, {%8,%9}, {%0,%1,%2,%3};"
        : "+f"(c[0]), "+f"(c[1]), "+f"(c[2]), "+f"(c[3])
        : "r"(a[0]), "r"(a[1]), "r"(a[2]), "r"(a[3]), "r"(b[0]), "r"(b[1]));
}

// ---------------- prep: all independent elementwise init in one kernel ----
#define PREP_TOT 609265

__device__ __forceinline__ void pack_one(__nv_bfloat16* dh, __nv_bfloat16* dl,
                                         const float* Wl, const float* Wr,
                                         int k1, int K, int n_off, int idx) {
    int n = idx / K, k = idx % K;
    float v = (k < k1) ? Wl[(size_t)k * 256 + n] : Wr[(size_t)(k - k1) * 256 + n];
    __nv_bfloat16 h = __float2bfloat16(v);
    __nv_bfloat16 l = __float2bfloat16(v - __bfloat162float(h));
    dh[(size_t)(n_off + n) * K + k] = h;
    dl[(size_t)(n_off + n) * K + k] = l;
}

__global__ void prep_kernel(const float* Wl1, const float* Wr1,
                            const float* Wl2, const float* Wr2,
                            const float* Wla, const float* Wra,
                            const float* Wlm, const float* Wrm,
                            const float* bla, const float* blm,
                            const float* Wa, const float* Wm,
                            const float* ba, const float* bm,
                            float* out) {
    int idx = blockIdx.x * blockDim.x + threadIdx.x;
    if (idx >= PREP_TOT) return;
    if (idx < 50000) {
        g_deg[idx] = 0;
    } else if (idx < 150000) {
        int i = idx - 50000;
        out[i] = (i < N_NODES) ? ba[0] : bm[0];
    } else if (idx < 215536) {
        pack_one(g_Bt1h, g_Bt1l, Wl1, Wr1, 128, 256, 0, idx - 150000);
    } else if (idx < 346608) {
        pack_one(g_Bt2h, g_Bt2l, Wl2, Wr2, 256, 512, 0, idx - 215536);
    } else if (idx < 477680) {
        pack_one(g_Bt3h, g_Bt3l, Wla, Wra, 256, 512, 0, idx - 346608);
    } else if (idx < 608752) {
        pack_one(g_Bt3h, g_Bt3l, Wlm, Wrm, 256, 512, 256, idx - 477680);
    } else if (idx < 609264) {
        int i = idx - 608752;
        if (i < 256) { g_b3[i] = bla[i]; g_hw[i] = Wa[i]; }
        else         { g_b3[i] = blm[i - 256]; g_hw[i] = Wm[i - 256]; }
    } else {
        g_bar = 0;
    }
}

// ---------------- fused CSR build: count -> scan -> scatter (persistent) ---
#define CSRB 148
#define CSRT 512
#define CHUNK 338        // 148 * 338 = 50024 >= 50000

__device__ __forceinline__ void gbar(int phase) {
    __syncthreads();
    __threadfence();                       // release: make prior stores L2-visible
    if (threadIdx.x == 0) {
        atomicAdd(&g_bar, 1);
        while (atomicAdd(&g_bar, 0) < phase * CSRB) { }
    }
    __syncthreads();
}

__global__ void __launch_bounds__(CSRT, 1)
csr_kernel(const void* __restrict__ ei) {
    __shared__ int s[CSRT];
    __shared__ int p[CSRT];
    __shared__ int sh_is64;
    const int tid = threadIdx.x, bid = blockIdx.x;

    if (tid == 0) {
        const int* e = (const int*)ei;
        int ok = 1;
        #pragma unroll 1
        for (int i = 0; i < 64; i++)
            if (e[2 * i + 1] != 0) { ok = 0; break; }
        sh_is64 = ok;
    }
    __syncthreads();
    const int is64 = sh_is64;

    // P0: degree count
    for (int e = bid * CSRT + tid; e < N_EDGES; e += CSRB * CSRT) {
        int d = is64 ? (int)((const long long*)ei)[(size_t)N_EDGES + e]
                     : ((const int*)ei)[N_EDGES + e];
        atomicAdd(&g_deg[d], 1);
    }
    gbar(1);

    // P1: per-block local inclusive scan of its CHUNK nodes
    const int i0 = bid * CHUNK;
    const int idx = i0 + tid;
    int v = (tid < CHUNK && idx < N_NODES) ? g_deg[idx] : 0;
    s[tid] = v;
    __syncthreads();
    for (int off = 1; off < CSRT; off <<= 1) {
        int t = (tid >= off) ? s[tid - off] : 0;
        __syncthreads();
        s[tid] += t;
        __syncthreads();
    }
    int incl = s[tid];
    if (tid == CSRT - 1) g_part[bid] = s[CSRT - 1];
    gbar(2);

    // P2: block 0 exclusive-scans the 148 partials
    if (bid == 0) {
        int o = (tid < CSRB) ? g_part[tid] : 0;
        p[tid] = o;
        __syncthreads();
        for (int off = 1; off < CSRT; off <<= 1) {
            int t = (tid >= off) ? p[tid - off] : 0;
            __syncthreads();
            p[tid] += t;
            __syncthreads();
        }
        if (tid < CSRB) g_part[tid] = p[tid] - o;   // exclusive
        if (tid == 0) g_rowptr[N_NODES] = p[CSRB - 1];
    }
    gbar(3);

    // P3: write rowptr / cursor
    int base = g_part[bid];
    if (tid < CHUNK && idx < N_NODES) {
        int ex = base + incl - v;
        g_rowptr[idx] = ex;
        g_cursor[idx] = ex;
    }
    gbar(4);

    // P4: scatter sources
    for (int e = bid * CSRT + tid; e < N_EDGES; e += CSRB * CSRT) {
        int sN, dN;
        if (is64) {
            sN = (int)((const long long*)ei)[e];
            dN = (int)((const long long*)ei)[(size_t)N_EDGES + e];
        } else {
            sN = ((const int*)ei)[e];
            dN = ((const int*)ei)[N_EDGES + e];
        }
        int pos = atomicAdd(&g_cursor[dN], 1);
        g_csrsrc[pos] = sN;
    }
}

// ---------------- segment max: one warp per node, 4-edge unroll -----------
__device__ __forceinline__ float4 max4(float4 a, float4 b) {
    return make_float4(fmaxf(a.x, b.x), fmaxf(a.y, b.y),
                       fmaxf(a.z, b.z), fmaxf(a.w, b.w));
}

template <int F>
__global__ void segmax_kernel(const float* __restrict__ feat, float* __restrict__ out) {
    int w = (blockIdx.x * blockDim.x + threadIdx.x) >> 5;
    int lane = threadIdx.x & 31;
    if (w >= N_NODES) return;
    int beg = g_rowptr[w];
    int end = g_rowptr[w + 1];
    constexpr int NV = F / 128;
    float4 m[NV];
    #pragma unroll
    for (int v = 0; v < NV; v++) m[v] = make_float4(-FLT_MAX, -FLT_MAX, -FLT_MAX, -FLT_MAX);

    int e = beg;
    for (; e + 3 < end; e += 4) {
        int s0 = g_csrsrc[e];
        int s1 = g_csrsrc[e + 1];
        int s2 = g_csrsrc[e + 2];
        int s3 = g_csrsrc[e + 3];
        const float4* r0 = (const float4*)(feat + (size_t)s0 * F);
        const float4* r1 = (const float4*)(feat + (size_t)s1 * F);
        const float4* r2 = (const float4*)(feat + (size_t)s2 * F);
        const float4* r3 = (const float4*)(feat + (size_t)s3 * F);
        #pragma unroll
        for (int v = 0; v < NV; v++) {
            float4 a = max4(r0[lane + 32 * v], r1[lane + 32 * v]);
            float4 b = max4(r2[lane + 32 * v], r3[lane + 32 * v]);
            m[v] = max4(m[v], max4(a, b));
        }
    }
    for (; e < end; e++) {
        int s0 = g_csrsrc[e];
        const float4* r0 = (const float4*)(feat + (size_t)s0 * F);
        #pragma unroll
        for (int v = 0; v < NV; v++) m[v] = max4(m[v], r0[lane + 32 * v]);
    }
    if (beg == end) {
        #pragma unroll
        for (int v = 0; v < NV; v++) m[v] = make_float4(0.f, 0.f, 0.f, 0.f);
    }
    float4* o = (float4*)(out + (size_t)w * F);
    #pragma unroll
    for (int v = 0; v < NV; v++) o[lane + 32 * v] = m[v];
}

// ---------------- mma.sync split-bf16 GEMM --------------------------------
#define ROWB 80
#define MAT_SZ (128 * ROWB)
#define OFF_AH 0
#define OFF_AL MAT_SZ
#define OFF_BH (2 * MAT_SZ)
#define OFF_BL (3 * MAT_SZ)
#define STAGE_SZ (4 * MAT_SZ)
#define GEMM_SMEM (2 * STAGE_SZ)

__global__ void __launch_bounds__(256)
mma_gemm(const float* __restrict__ A1, const float* __restrict__ A2, int k1, int k2,
         const __nv_bfloat16* __restrict__ Bth, const __nv_bfloat16* __restrict__ Btl,
         const float* __restrict__ bias, const float* __restrict__ headw,
         float* __restrict__ Cout, int mode) {
    extern __shared__ char smem[];
    const uint32_t sb = smem_u32(smem);
    const int tid = threadIdx.x;
    const int lane = tid & 31, wid = tid >> 5;
    const int warp_m = (wid & 3) * 32;
    const int warp_n = (wid >> 2) * 64;
    const int row0 = blockIdx.x * GEMM_TM;
    const int nb = blockIdx.y * 128;
    const int K = k1 + k2;
    const int NCH = K / KC;
    const int ach = k1 / KC;

    const int a_row_l = (lane & 7) + ((lane >> 3) & 1) * 8;
    const int a_csel  = lane >> 4;
    const int b_row_l = (lane & 7) + ((lane >> 3) & 2) * 4;
    const int b_csel  = (lane >> 3) & 1;

    const int ar = tid >> 1;
    const int ah = tid & 1;
    const int myrow = row0 + ar;
    const bool rok = myrow < N_NODES;

    float acc[2][8][4];
    #pragma unroll
    for (int mi = 0; mi < 2; mi++)
        #pragma unroll
        for (int ni = 0; ni < 8; ni++)
            #pragma unroll
            for (int j = 0; j < 4; j++) acc[mi][ni][j] = 0.f;

    float fa[16];
    uint4 pbh[2], pbl[2];

    // ---- load chunk 0 ----
    {
        const float* A = (0 < ach) ? A1 : A2;
        int stride = (0 < ach) ? k1 : k2;
        const float4* src = (const float4*)(A + (size_t)myrow * stride + ah * 16);
        #pragma unroll
        for (int i = 0; i < 4; i++) {
            float4 f = rok ? src[i] : make_float4(0.f, 0.f, 0.f, 0.f);
            fa[i * 4 + 0] = f.x; fa[i * 4 + 1] = f.y; fa[i * 4 + 2] = f.z; fa[i * 4 + 3] = f.w;
        }
        const uint4* sh = (const uint4*)(Bth + (size_t)(nb + ar) * K + ah * 16);
        const uint4* sl = (const uint4*)(Btl + (size_t)(nb + ar) * K + ah * 16);
        pbh[0] = sh[0]; pbh[1] = sh[1];
        pbl[0] = sl[0]; pbl[1] = sl[1];
    }
    {
        char* stg = smem;
        uint32_t hi[8], lo[8];
        #pragma unroll
        for (int i = 0; i < 8; i++) {
            float x = fa[2 * i], y = fa[2 * i + 1];
            __nv_bfloat162 h2 = __floats2bfloat162_rn(x, y);
            float lx = x - __bfloat162float(h2.x);
            float ly = y - __bfloat162float(h2.y);
            __nv_bfloat162 l2 = __floats2bfloat162_rn(lx, ly);
            hi[i] = b2u(h2); lo[i] = b2u(l2);
        }
        char* da = stg + ar * ROWB + ah * 32;
        *(uint4*)(da + OFF_AH)      = make_uint4(hi[0], hi[1], hi[2], hi[3]);
        *(uint4*)(da + OFF_AH + 16) = make_uint4(hi[4], hi[5], hi[6], hi[7]);
        *(uint4*)(da + OFF_AL)      = make_uint4(lo[0], lo[1], lo[2], lo[3]);
        *(uint4*)(da + OFF_AL + 16) = make_uint4(lo[4], lo[5], lo[6], lo[7]);
        *(uint4*)(da + OFF_BH)      = pbh[0];
        *(uint4*)(da + OFF_BH + 16) = pbh[1];
        *(uint4*)(da + OFF_BL)      = pbl[0];
        *(uint4*)(da + OFF_BL + 16) = pbl[1];
    }
    __syncthreads();

    for (int ch = 0; ch < NCH; ++ch) {
        const bool more = (ch + 1 < NCH);
        if (more) {
            int c = ch + 1;
            const float* A;
            int stride, kloc;
            if (c < ach) { A = A1; stride = k1; kloc = c * KC; }
            else         { A = A2; stride = k2; kloc = (c - ach) * KC; }
            const float4* src = (const float4*)(A + (size_t)myrow * stride + kloc + ah * 16);
            #pragma unroll
            for (int i = 0; i < 4; i++) {
                float4 f = rok ? src[i] : make_float4(0.f, 0.f, 0.f, 0.f);
                fa[i * 4 + 0] = f.x; fa[i * 4 + 1] = f.y; fa[i * 4 + 2] = f.z; fa[i * 4 + 3] = f.w;
            }
            const uint4* sh = (const uint4*)(Bth + (size_t)(nb + ar) * K + c * KC + ah * 16);
            const uint4* sl = (const uint4*)(Btl + (size_t)(nb + ar) * K + c * KC + ah * 16);
            pbh[0] = sh[0]; pbh[1] = sh[1];
            pbl[0] = sl[0]; pbl[1] = sl[1];
        }

        {
            const uint32_t stg = sb + (ch & 1) * STAGE_SZ;
            #pragma unroll
            for (int kb = 0; kb < 2; kb++) {
                uint32_t Ah[2][4], Al[2][4];
                #pragma unroll
                for (int mi = 0; mi < 2; mi++) {
                    uint32_t addr = stg + (warp_m + mi * 16 + a_row_l) * ROWB +
                                    (kb * 2 + a_csel) * 16;
                    ldsm_x4(Ah[mi], addr + OFF_AH);
                    ldsm_x4(Al[mi], addr + OFF_AL);
                }
                uint32_t Bh[4][4], Bl[4][4];
                #pragma unroll
                for (int nt = 0; nt < 4; nt++) {
                    uint32_t addr = stg + (warp_n + nt * 16 + b_row_l) * ROWB +
                                    (kb * 2 + b_csel) * 16;
                    ldsm_x4(Bh[nt], addr + OFF_BH);
                    ldsm_x4(Bl[nt], addr + OFF_BL);
                }
                #pragma unroll
                for (int mi = 0; mi < 2; mi++)
                    #pragma unroll
                    for (int ni = 0; ni < 8; ni++) {
                        const uint32_t* bp  = &Bh[ni >> 1][(ni & 1) * 2];
                        const uint32_t* blp = &Bl[ni >> 1][(ni & 1) * 2];
                        mma_bf16(acc[mi][ni], Ah[mi], bp);
                        mma_bf16(acc[mi][ni], Al[mi], bp);
                        mma_bf16(acc[mi][ni], Ah[mi], blp);
                    }
            }
        }

        if (more) {
            char* stg = smem + ((ch + 1) & 1) * STAGE_SZ;
            uint32_t hi[8], lo[8];
            #pragma unroll
            for (int i = 0; i < 8; i++) {
                float x = fa[2 * i], y = fa[2 * i + 1];
                __nv_bfloat162 h2 = __floats2bfloat162_rn(x, y);
                float lx = x - __bfloat162float(h2.x);
                float ly = y - __bfloat162float(h2.y);
                __nv_bfloat162 l2 = __floats2bfloat162_rn(lx, ly);
                hi[i] = b2u(h2); lo[i] = b2u(l2);
            }
            char* da = stg + ar * ROWB + ah * 32;
            *(uint4*)(da + OFF_AH)      = make_uint4(hi[0], hi[1], hi[2], hi[3]);
            *(uint4*)(da + OFF_AH + 16) = make_uint4(hi[4], hi[5], hi[6], hi[7]);
            *(uint4*)(da + OFF_AL)      = make_uint4(lo[0], lo[1], lo[2], lo[3]);
            *(uint4*)(da + OFF_AL + 16) = make_uint4(lo[4], lo[5], lo[6], lo[7]);
            *(uint4*)(da + OFF_BH)      = pbh[0];
            *(uint4*)(da + OFF_BH + 16) = pbh[1];
            *(uint4*)(da + OFF_BL)      = pbl[0];
            *(uint4*)(da + OFF_BL + 16) = pbl[1];
        }
        __syncthreads();
    }

    // ---- epilogue ----
    const int t4r = lane >> 2;
    const int t4c = (lane & 3) * 2;
    if (mode == 0) {
        #pragma unroll
        for (int mi = 0; mi < 2; mi++) {
            #pragma unroll
            for (int half = 0; half < 2; half++) {
                int row = row0 + warp_m + mi * 16 + half * 8 + t4r;
                if (row >= N_NODES) continue;
                float* cp = Cout + (size_t)row * 256;
                #pragma unroll
                for (int ni = 0; ni < 8; ni++) {
                    int col = nb + warp_n + ni * 8 + t4c;
                    float v0 = fmaxf(acc[mi][ni][half * 2 + 0] + bias[col], 0.f);
                    float v1 = fmaxf(acc[mi][ni][half * 2 + 1] + bias[col + 1], 0.f);
                    *(float2*)(cp + col) = make_float2(v0, v1);
                }
            }
        }
    } else {
        const int branch = nb >> 8;
        #pragma unroll
        for (int mi = 0; mi < 2; mi++) {
            float s[2] = {0.f, 0.f};
            #pragma unroll
            for (int half = 0; half < 2; half++) {
                #pragma unroll
                for (int ni = 0; ni < 8; ni++) {
                    int col = nb + warp_n + ni * 8 + t4c;
                    float v0 = fmaxf(acc[mi][ni][half * 2 + 0] + bias[col], 0.f);
                    float v1 = fmaxf(acc[mi][ni][half * 2 + 1] + bias[col + 1], 0.f);
                    s[half] += v0 * headw[col] + v1 * headw[col + 1];
                }
            }
            #pragma unroll
            for (int half = 0; half < 2; half++) {
                float v = s[half];
                v += __shfl_xor_sync(0xffffffffu, v, 1);
                v += __shfl_xor_sync(0xffffffffu, v, 2);
                int row = row0 + warp_m + mi * 16 + half * 8 + t4r;
                if ((lane & 3) == 0 && row < N_NODES)
                    atomicAdd(&Cout[(size_t)branch * N_NODES + row], v);
            }
        }
    }
}

// ---------------- launch ----------------
extern "C" void kernel_launch(void* const* d_in, const int* in_sizes, int n_in,
                              void* d_out, int out_size) {
    const float* x   = (const float*)d_in[0];
    const void*  ei  = d_in[1];
    const float* Wl1 = (const float*)d_in[2];
    const float* bl1 = (const float*)d_in[3];
    const float* Wr1 = (const float*)d_in[4];
    const float* Wl2 = (const float*)d_in[5];
    const float* bl2 = (const float*)d_in[6];
    const float* Wr2 = (const float*)d_in[7];
    const float* Wla = (const float*)d_in[8];
    const float* bla = (const float*)d_in[9];
    const float* Wra = (const float*)d_in[10];
    const float* Wa  = (const float*)d_in[11];
    const float* ba  = (const float*)d_in[12];
    const float* Wlm = (const float*)d_in[13];
    const float* blm = (const float*)d_in[14];
    const float* Wrm = (const float*)d_in[15];
    const float* Wm  = (const float*)d_in[16];
    const float* bm  = (const float*)d_in[17];
    float* out = (float*)d_out;

    float* AGG; cudaGetSymbolAddress((void**)&AGG, g_AGG);
    float* H1;  cudaGetSymbolAddress((void**)&H1,  g_H1);
    float* H2;  cudaGetSymbolAddress((void**)&H2,  g_H2);
    __nv_bfloat16 *Bt1h, *Bt1l, *Bt2h, *Bt2l, *Bt3h, *Bt3l;
    cudaGetSymbolAddress((void**)&Bt1h, g_Bt1h);
    cudaGetSymbolAddress((void**)&Bt1l, g_Bt1l);
    cudaGetSymbolAddress((void**)&Bt2h, g_Bt2h);
    cudaGetSymbolAddress((void**)&Bt2l, g_Bt2l);
    cudaGetSymbolAddress((void**)&Bt3h, g_Bt3h);
    cudaGetSymbolAddress((void**)&Bt3l, g_Bt3l);
    float *b3, *hw;
    cudaGetSymbolAddress((void**)&b3, g_b3);
    cudaGetSymbolAddress((void**)&hw, g_hw);

    cudaFuncSetAttribute(mma_gemm, cudaFuncAttributeMaxDynamicSharedMemorySize, GEMM_SMEM);

    const int TB = 256;
    const int gemm_gx = (N_NODES + GEMM_TM - 1) / GEMM_TM;   // 391
    const int warp_blocks = (N_NODES * 32 + TB - 1) / TB;

    // 1: all elementwise prep (zero deg, packs, out init, barrier reset)
    prep_kernel<<<(PREP_TOT + TB - 1) / TB, TB>>>(Wl1, Wr1, Wl2, Wr2, Wla, Wra,
                                                  Wlm, Wrm, bla, blm, Wa, Wm,
                                                  ba, bm, out);
    // 2: fused CSR build (persistent, software grid barriers)
    csr_kernel<<<CSRB, CSRT>>>(ei);

    // 3-4: layer 1  (launch #4 = mma_gemm -> ncu capture target)
    segmax_kernel<F_IN><<<warp_blocks, TB>>>(x, AGG);
    mma_gemm<<<dim3(gemm_gx, 2), 256, GEMM_SMEM>>>(AGG, x, 128, 128, Bt1h, Bt1l,
                                                   bl1, nullptr, H1, 0);
    // 5-6: layer 2
    segmax_kernel<H><<<warp_blocks, TB>>>(H1, AGG);
    mma_gemm<<<dim3(gemm_gx, 2), 256, GEMM_SMEM>>>(AGG, H1, 256, 256, Bt2h, Bt2l,
                                                   bl2, nullptr, H2, 0);
    // 7-8: shared aggregation + fused dual-branch layer 3 with head epilogue
    segmax_kernel<H><<<warp_blocks, TB>>>(H2, AGG);
    mma_gemm<<<dim3(gemm_gx, 4), 256, GEMM_SMEM>>>(AGG, H2, 256, 256, Bt3h, Bt3l,
                                                   b3, hw, out, 1);
}